// round 5
// baseline (speedup 1.0000x reference)
#include <cuda_runtime.h>
#include <cuda_bf16.h>
#include <cstdint>
#include <cstddef>

#define NN   50000
#define EE   800000
#define RR   4
#define NB   (NN * RR)
#define DIN  128
#define DH   256
#define EPSF 1e-10f

// ---------------- scratch (static device globals) ------------------------------
__device__ int   g_deg[NB];
__device__ int   g_off[NB];
__device__ int   g_pos[NB];
__device__ int   g_bsum[256];
__device__ int   g_eidx[EE];

// split bf16 hi/lo planes for all GEMM A operands
__device__ uint16_t g_xh[(size_t)NN * DIN],      g_xl[(size_t)NN * DIN];
__device__ uint16_t g_aggh[(size_t)NN * RR * DH], g_aggl[(size_t)NN * RR * DH];
__device__ uint16_t g_th[(size_t)NN * DH],       g_tl[(size_t)NN * DH];
__device__ uint16_t g_hh[(size_t)NN * DH],       g_hl[(size_t)NN * DH];
__device__ float    g_h[(size_t)NN * DH];          // fp32 h for layer-2 gather
__device__ float    g_pg[(size_t)NN * 2 * DH];     // proj|gate pre-activations

// pre-split weights
#define OW_REL1  0
#define OW_LOOP1 131072
#define OW_HP1   163840
#define OW_HT1   229376
#define OW_REL2  294912
#define OW_LOOP2 557056
#define OW_HP2   622592
#define OW_HT2   688128
#define WTOT     753664
__device__ uint16_t g_whi[WTOT];
__device__ uint16_t g_wlo[WTOT];

// ---------------- CSR build ------------------------------------------------------
__global__ void zero_i(int* __restrict__ p, int n) {
    int i = blockIdx.x * blockDim.x + threadIdx.x;
    if (i < n) p[i] = 0;
}

__global__ void count_kernel(const int* __restrict__ dst, const int* __restrict__ rel, int E) {
    int e = blockIdx.x * blockDim.x + threadIdx.x;
    if (e < E) atomicAdd(&g_deg[dst[e] * RR + rel[e]], 1);
}

__global__ void scan_block(const int* __restrict__ in, int* __restrict__ out,
                           int* __restrict__ bsum, int n) {
    __shared__ int wsum[8];
    int base = blockIdx.x * 1024;
    int t = threadIdx.x;
    int lane = t & 31, w = t >> 5;
    int v[4], s = 0;
#pragma unroll
    for (int j = 0; j < 4; j++) {
        int i = base + t * 4 + j;
        v[j] = (i < n) ? in[i] : 0;
        s += v[j];
    }
    int ps = s;
#pragma unroll
    for (int d = 1; d < 32; d <<= 1) {
        int y = __shfl_up_sync(~0u, ps, d);
        if (lane >= d) ps += y;
    }
    if (lane == 31) wsum[w] = ps;
    __syncthreads();
    if (w == 0) {
        int x = (lane < 8) ? wsum[lane] : 0;
#pragma unroll
        for (int d = 1; d < 8; d <<= 1) {
            int y = __shfl_up_sync(~0u, x, d);
            if (lane >= d) x += y;
        }
        if (lane < 8) wsum[lane] = x;
    }
    __syncthreads();
    int excl = ps - s + (w > 0 ? wsum[w - 1] : 0);
#pragma unroll
    for (int j = 0; j < 4; j++) {
        int i = base + t * 4 + j;
        if (i < n) out[i] = excl;
        excl += v[j];
    }
    if (t == 255 && bsum) bsum[blockIdx.x] = (w > 0 ? wsum[w - 1] : 0) + ps;
}

__global__ void scan_add(int* __restrict__ off, const int* __restrict__ bsum, int n) {
    int i = blockIdx.x * 1024 + threadIdx.x * 4;
    int a = bsum[blockIdx.x];
#pragma unroll
    for (int j = 0; j < 4; j++)
        if (i + j < n) off[i + j] += a;
}

__global__ void place_kernel(const int* __restrict__ src, const int* __restrict__ dst,
                             const int* __restrict__ rel, int E) {
    int e = blockIdx.x * blockDim.x + threadIdx.x;
    if (e >= E) return;
    int b = dst[e] * RR + rel[e];
    int slot = g_off[b] + atomicAdd(&g_pos[b], 1);
    g_eidx[slot] = src[e];
}

// ---------------- split helpers ---------------------------------------------------
__device__ __forceinline__ void split_bf(float v, uint16_t& h, uint16_t& l) {
    __nv_bfloat16 hb = __float2bfloat16_rn(v);
    float res = v - __bfloat162float(hb);
    h = __bfloat16_as_ushort(hb);
    l = __bfloat16_as_ushort(__float2bfloat16_rn(res));
}

__global__ void split_w(const float* __restrict__ w, uint16_t* __restrict__ hi,
                        uint16_t* __restrict__ lo, int n) {
    int i = blockIdx.x * blockDim.x + threadIdx.x;
    if (i >= n) return;
    uint16_t h, l;
    split_bf(w[i], h, l);
    hi[i] = h;
    lo[i] = l;
}

// ---------------- gather aggregation (writes split planes) ------------------------
template <int D>
__global__ void agg_gather(const float* __restrict__ x) {
    int gw = (blockIdx.x * blockDim.x + threadIdx.x) >> 5;
    int lane = threadIdx.x & 31;
    if (gw >= NB) return;
    int start = g_off[gw];
    int n = g_deg[gw];
    const float4* X = (const float4*)x;
    float4 a0 = make_float4(0.f, 0.f, 0.f, 0.f);
    float4 a1 = make_float4(0.f, 0.f, 0.f, 0.f);
    int k = 0;
    for (; k + 2 <= n; k += 2) {
        int s0 = g_eidx[start + k];
        int s1 = g_eidx[start + k + 1];
        const float4* r0 = X + (size_t)s0 * (D / 4);
        const float4* r1 = X + (size_t)s1 * (D / 4);
        float4 v0 = r0[lane], w0 = r1[lane];
        a0.x += v0.x + w0.x; a0.y += v0.y + w0.y;
        a0.z += v0.z + w0.z; a0.w += v0.w + w0.w;
        if (D == 256) {
            float4 v1 = r0[lane + 32], w1 = r1[lane + 32];
            a1.x += v1.x + w1.x; a1.y += v1.y + w1.y;
            a1.z += v1.z + w1.z; a1.w += v1.w + w1.w;
        }
    }
    if (k < n) {
        int s0 = g_eidx[start + k];
        const float4* r0 = X + (size_t)s0 * (D / 4);
        float4 v0 = r0[lane];
        a0.x += v0.x; a0.y += v0.y; a0.z += v0.z; a0.w += v0.w;
        if (D == 256) {
            float4 v1 = r0[lane + 32];
            a1.x += v1.x; a1.y += v1.y; a1.z += v1.z; a1.w += v1.w;
        }
    }
    float inv = 1.0f / ((float)n + EPSF);
    a0.x *= inv; a0.y *= inv; a0.z *= inv; a0.w *= inv;
    uint16_t h0, h1, h2, h3, l0, l1, l2, l3;
    split_bf(a0.x, h0, l0); split_bf(a0.y, h1, l1);
    split_bf(a0.z, h2, l2); split_bf(a0.w, h3, l3);
    uint2 hw = make_uint2((uint32_t)h0 | ((uint32_t)h1 << 16),
                          (uint32_t)h2 | ((uint32_t)h3 << 16));
    uint2 lw = make_uint2((uint32_t)l0 | ((uint32_t)l1 << 16),
                          (uint32_t)l2 | ((uint32_t)l3 << 16));
    ((uint2*)(g_aggh + (size_t)gw * D))[lane] = hw;
    ((uint2*)(g_aggl + (size_t)gw * D))[lane] = lw;
    if (D == 256) {
        a1.x *= inv; a1.y *= inv; a1.z *= inv; a1.w *= inv;
        split_bf(a1.x, h0, l0); split_bf(a1.y, h1, l1);
        split_bf(a1.z, h2, l2); split_bf(a1.w, h3, l3);
        hw = make_uint2((uint32_t)h0 | ((uint32_t)h1 << 16),
                        (uint32_t)h2 | ((uint32_t)h3 << 16));
        lw = make_uint2((uint32_t)l0 | ((uint32_t)l1 << 16),
                        (uint32_t)l2 | ((uint32_t)l3 << 16));
        ((uint2*)(g_aggh + (size_t)gw * D))[lane + 32] = hw;
        ((uint2*)(g_aggl + (size_t)gw * D))[lane + 32] = lw;
    }
}

// ---------------- highway elementwise ----------------------------------------------
// t reconstructed from hi/lo planes; writes fp32 h (optional) and hi/lo planes (optional)
__global__ void highway_kernel(const uint16_t* __restrict__ th, const uint16_t* __restrict__ tl,
                               const float* __restrict__ pg,
                               float* __restrict__ hf,
                               uint16_t* __restrict__ hh, uint16_t* __restrict__ hl,
                               int M) {
    int i = blockIdx.x * blockDim.x + threadIdx.x;   // pairs
    if (i >= M * (DH / 2)) return;
    int e0 = i * 2;
    int n = e0 >> 8;
    int c = e0 & 255;
    const float* row = pg + (size_t)n * (2 * DH);
    float p0 = fmaxf(row[c], 0.f), p1 = fmaxf(row[c + 1], 0.f);
    float q0 = row[DH + c], q1 = row[DH + c + 1];
    float s0 = 1.0f / (1.0f + expf(-q0));
    float s1 = 1.0f / (1.0f + expf(-q1));
    float t0 = __bfloat162float(__ushort_as_bfloat16(th[e0])) +
               __bfloat162float(__ushort_as_bfloat16(tl[e0]));
    float t1 = __bfloat162float(__ushort_as_bfloat16(th[e0 + 1])) +
               __bfloat162float(__ushort_as_bfloat16(tl[e0 + 1]));
    float v0 = s0 * p0 + (1.0f - s0) * t0;
    float v1 = s1 * p1 + (1.0f - s1) * t1;
    if (hf) *(float2*)(hf + e0) = make_float2(v0, v1);
    if (hh) {
        uint16_t h0, h1, l0, l1;
        split_bf(v0, h0, l0);
        split_bf(v1, h1, l1);
        *(uint32_t*)(hh + e0) = (uint32_t)h0 | ((uint32_t)h1 << 16);
        *(uint32_t*)(hl + e0) = (uint32_t)l0 | ((uint32_t)l1 << 16);
    }
}

// ---------------- mma.sync helpers ---------------------------------------------------
__device__ __forceinline__ uint32_t smem_u32(const void* p) {
    uint32_t a;
    asm("{ .reg .u64 t; cvta.to.shared.u64 t, %1; cvt.u32.u64 %0, t; }" : "=r"(a) : "l"(p));
    return a;
}
__device__ __forceinline__ void ldsm_x4(uint32_t* r, uint32_t addr) {
    asm volatile("ldmatrix.sync.aligned.m8n8.x4.shared.b16 {%0,%1,%2,%3}, [%4];"
                 : "=r"(r[0]), "=r"(r[1]), "=r"(r[2]), "=r"(r[3]) : "r"(addr));
}
__device__ __forceinline__ void ldsm_x4_t(uint32_t* r, uint32_t addr) {
    asm volatile("ldmatrix.sync.aligned.m8n8.x4.trans.shared.b16 {%0,%1,%2,%3}, [%4];"
                 : "=r"(r[0]), "=r"(r[1]), "=r"(r[2]), "=r"(r[3]) : "r"(addr));
}
__device__ __forceinline__ void mma_bf16(float* d, const uint32_t* a, uint32_t b0, uint32_t b1) {
    asm volatile(
        "mma.sync.aligned.m16n8k16.row.col.f32.bf16.bf16.f32 "
        "{%0,%1,%2,%3}, {%4,%5,%6,%7}, {%8,%9}, {%0,%1,%2,%3};"
        : "+f"(d[0]), "+f"(d[1]), "+f"(d[2]), "+f"(d[3])
        : "r"(a[0]), "r"(a[1]), "r"(a[2]), "r"(a[3]), "r"(b0), "r"(b1));
}

// ---------------- bf16 pre-split dual-A GEMM -----------------------------------------
// C = act( A1 @ W1 + A2 @ W2 + b1 (+b2) ); A and W both pre-split bf16 hi/lo planes.
// Output: either fp32 Cf, or split planes Ch/Cl.
#define A_STRIDE 80
#define A_BYTES  (128 * A_STRIDE)
#define B_BYTES  (32 * 256)
#define STAGE_BYTES (A_BYTES + B_BYTES)

__global__ void __launch_bounds__(256)
gemm_mma(const uint16_t* __restrict__ A1h, const uint16_t* __restrict__ A1l, int K1,
         const uint16_t* __restrict__ W1h, const uint16_t* __restrict__ W1l,
         const uint16_t* __restrict__ A2h, const uint16_t* __restrict__ A2l, int K2,
         const uint16_t* __restrict__ W2h, const uint16_t* __restrict__ W2l,
         const float* __restrict__ b1, const float* __restrict__ b2,
         float* __restrict__ Cf, uint16_t* __restrict__ Ch, uint16_t* __restrict__ Cl,
         int M, int ldc, int act) {
    __shared__ char sm[2 * STAGE_BYTES];

    int tid  = threadIdx.x;
    int warp = tid >> 5;
    int lane = tid & 31;
    int warpM = warp >> 1;
    int warpN = warp & 1;
    int rowBase = blockIdx.x * 128;
    int colBase = blockIdx.y * 128;

    float acc[2][8][4];
#pragma unroll
    for (int i = 0; i < 2; i++)
#pragma unroll
        for (int j = 0; j < 8; j++)
#pragma unroll
            for (int q = 0; q < 4; q++) acc[i][j][q] = 0.f;

    int nt1 = K1 >> 4, nt2 = K2 >> 4;
    int nt = nt1 + nt2;

    int arow = tid >> 1, ahalf = tid & 1;       // A: 128 rows x 2 half-cols of 8
    uint4 ah4, al4;
    uint2 bhv[2], blv[2];

    // prefetch t = 0
    {
        const uint16_t *Ah = A1h, *Al = A1l, *Wh = W1h, *Wl = W1l;
        int K = K1, k0 = 0;
        if (nt1 == 0) { Ah = A2h; Al = A2l; Wh = W2h; Wl = W2l; K = K2; }
        int gr = rowBase + arow;
        if (gr < M) {
            size_t ai = (size_t)gr * K + k0 + ahalf * 8;
            ah4 = *(const uint4*)(Ah + ai);
            al4 = *(const uint4*)(Al + ai);
        } else {
            ah4 = make_uint4(0, 0, 0, 0);
            al4 = make_uint4(0, 0, 0, 0);
        }
#pragma unroll
        for (int i = 0; i < 2; ++i) {
            int li = tid + i * 256;
            int r = li >> 5, c4 = li & 31;
            size_t wi = (size_t)(k0 + r) * DH + colBase + c4 * 4;
            bhv[i] = *(const uint2*)(Wh + wi);
            blv[i] = *(const uint2*)(Wl + wi);
        }
    }

    for (int t = 0; t < nt; ++t) {
        char* As = sm + (t & 1) * STAGE_BYTES;
        char* Bs = As + A_BYTES;

        // ---- STS (no math) ----
        *(uint4*)(As + arow * A_STRIDE + ahalf * 16)      = ah4;
        *(uint4*)(As + arow * A_STRIDE + 32 + ahalf * 16) = al4;
#pragma unroll
        for (int i = 0; i < 2; ++i) {
            int li = tid + i * 256;
            int r = li >> 5, c4 = li & 31;
            uint32_t sw = (uint32_t)(c4 * 8) ^ ((r & 7) << 4);
            *(uint2*)(Bs + r * 256 + sw)        = bhv[i];
            *(uint2*)(Bs + (16 + r) * 256 + sw) = blv[i];
        }
        __syncthreads();

        // ---- prefetch t+1 ----
        if (t + 1 < nt) {
            int tn = t + 1;
            const uint16_t *Ah, *Al, *Wh, *Wl;
            int K, k0;
            if (tn < nt1) { Ah = A1h; Al = A1l; Wh = W1h; Wl = W1l; K = K1; k0 = tn * 16; }
            else { Ah = A2h; Al = A2l; Wh = W2h; Wl = W2l; K = K2; k0 = (tn - nt1) * 16; }
            int gr = rowBase + arow;
            if (gr < M) {
                size_t ai = (size_t)gr * K + k0 + ahalf * 8;
                ah4 = *(const uint4*)(Ah + ai);
                al4 = *(const uint4*)(Al + ai);
            } else {
                ah4 = make_uint4(0, 0, 0, 0);
                al4 = make_uint4(0, 0, 0, 0);
            }
#pragma unroll
            for (int i = 0; i < 2; ++i) {
                int li = tid + i * 256;
                int r = li >> 5, c4 = li & 31;
                size_t wi = (size_t)(k0 + r) * DH + colBase + c4 * 4;
                bhv[i] = *(const uint2*)(Wh + wi);
                blv[i] = *(const uint2*)(Wl + wi);
            }
        }

        // ---- fragments ----
        uint32_t aBase = smem_u32(As);
        uint32_t bBase = smem_u32(Bs);
        uint32_t ahi[2][4], alo[2][4], bhi[4][4], blo[4][4];
#pragma unroll
        for (int mt = 0; mt < 2; ++mt) {
            int row = warpM * 32 + mt * 16 + (lane & 15);
            uint32_t ad = aBase + row * A_STRIDE + ((lane >> 4) * 8) * 2;
            ldsm_x4(ahi[mt], ad);
            ldsm_x4(alo[mt], ad + 32);
        }
#pragma unroll
        for (int bt = 0; bt < 4; ++bt) {
            int k = lane & 15;
            uint32_t cb = (uint32_t)(warpN * 128 + bt * 32 + (lane >> 4) * 16);
            uint32_t bd = bBase + k * 256 + (cb ^ ((k & 7) << 4));
            ldsm_x4_t(bhi[bt], bd);
            ldsm_x4_t(blo[bt], bd + 16 * 256);
        }

        // ---- 3-term split mma ----
#pragma unroll
        for (int mt = 0; mt < 2; ++mt) {
#pragma unroll
            for (int bt = 0; bt < 4; ++bt) {
                mma_bf16(acc[mt][bt * 2 + 0], ahi[mt], bhi[bt][0], bhi[bt][1]);
                mma_bf16(acc[mt][bt * 2 + 1], ahi[mt], bhi[bt][2], bhi[bt][3]);
                mma_bf16(acc[mt][bt * 2 + 0], ahi[mt], blo[bt][0], blo[bt][1]);
                mma_bf16(acc[mt][bt * 2 + 1], ahi[mt], blo[bt][2], blo[bt][3]);
                mma_bf16(acc[mt][bt * 2 + 0], alo[mt], bhi[bt][0], bhi[bt][1]);
                mma_bf16(acc[mt][bt * 2 + 1], alo[mt], bhi[bt][2], bhi[bt][3]);
            }
        }
    }

    // ---- epilogue ----
#pragma unroll
    for (int mt = 0; mt < 2; ++mt) {
        int r0 = rowBase + warpM * 32 + mt * 16 + (lane >> 2);
#pragma unroll
        for (int j = 0; j < 8; ++j) {
            int col = colBase + warpN * 64 + j * 8 + (lane & 3) * 2;
            float bias0 = b1[col], bias1 = b1[col + 1];
            if (b2) { bias0 += b2[col]; bias1 += b2[col + 1]; }
            float v0 = acc[mt][j][0] + bias0;
            float v1 = acc[mt][j][1] + bias1;
            float v2 = acc[mt][j][2] + bias0;
            float v3 = acc[mt][j][3] + bias1;
            if (act) {
                v0 = fmaxf(v0, 0.f); v1 = fmaxf(v1, 0.f);
                v2 = fmaxf(v2, 0.f); v3 = fmaxf(v3, 0.f);
            }
            if (Ch) {
                uint16_t h0, h1, l0, l1;
                if (r0 < M) {
                    split_bf(v0, h0, l0); split_bf(v1, h1, l1);
                    *(uint32_t*)(Ch + (size_t)r0 * ldc + col) = (uint32_t)h0 | ((uint32_t)h1 << 16);
                    *(uint32_t*)(Cl + (size_t)r0 * ldc + col) = (uint32_t)l0 | ((uint32_t)l1 << 16);
                }
                if (r0 + 8 < M) {
                    split_bf(v2, h0, l0); split_bf(v3, h1, l1);
                    *(uint32_t*)(Ch + (size_t)(r0 + 8) * ldc + col) = (uint32_t)h0 | ((uint32_t)h1 << 16);
                    *(uint32_t*)(Cl + (size_t)(r0 + 8) * ldc + col) = (uint32_t)l0 | ((uint32_t)l1 << 16);
                }
            } else {
                if (r0 < M)     *(float2*)(Cf + (size_t)r0 * ldc + col)       = make_float2(v0, v1);
                if (r0 + 8 < M) *(float2*)(Cf + (size_t)(r0 + 8) * ldc + col) = make_float2(v2, v3);
            }
        }
    }
}

// ---------------- launcher ----------------------------------------------------------
extern "C" void kernel_launch(void* const* d_in, const int* in_sizes, int n_in,
                              void* d_out, int out_size) {
    const float* x       = (const float*)d_in[0];
    const int*   src     = (const int*)d_in[1];
    const int*   dst     = (const int*)d_in[2];
    const int*   rel     = (const int*)d_in[3];
    const float* rel_w1  = (const float*)d_in[4];
    const float* rel_b1  = (const float*)d_in[5];
    const float* loop_w1 = (const float*)d_in[6];
    const float* loop_b1 = (const float*)d_in[7];
    const float* hp_w1   = (const float*)d_in[8];
    const float* hp_b1   = (const float*)d_in[9];
    const float* ht_w1   = (const float*)d_in[10];
    const float* ht_b1   = (const float*)d_in[11];
    const float* rel_w2  = (const float*)d_in[12];
    const float* rel_b2  = (const float*)d_in[13];
    const float* loop_w2 = (const float*)d_in[14];
    const float* loop_b2 = (const float*)d_in[15];
    const float* hp_w2   = (const float*)d_in[16];
    const float* hp_b2   = (const float*)d_in[17];
    const float* ht_w2   = (const float*)d_in[18];
    const float* ht_b2   = (const float*)d_in[19];
    float* out = (float*)d_out;

    float *hbuf, *pg;
    int *deg, *off, *pos, *bsum;
    uint16_t *whi, *wlo, *xh, *xl, *aggh, *aggl, *th, *tl, *hh, *hl;
    cudaGetSymbolAddress((void**)&hbuf, g_h);
    cudaGetSymbolAddress((void**)&pg,   g_pg);
    cudaGetSymbolAddress((void**)&deg,  g_deg);
    cudaGetSymbolAddress((void**)&off,  g_off);
    cudaGetSymbolAddress((void**)&pos,  g_pos);
    cudaGetSymbolAddress((void**)&bsum, g_bsum);
    cudaGetSymbolAddress((void**)&whi,  g_whi);
    cudaGetSymbolAddress((void**)&wlo,  g_wlo);
    cudaGetSymbolAddress((void**)&xh,   g_xh);
    cudaGetSymbolAddress((void**)&xl,   g_xl);
    cudaGetSymbolAddress((void**)&aggh, g_aggh);
    cudaGetSymbolAddress((void**)&aggl, g_aggl);
    cudaGetSymbolAddress((void**)&th,   g_th);
    cudaGetSymbolAddress((void**)&tl,   g_tl);
    cudaGetSymbolAddress((void**)&hh,   g_hh);
    cudaGetSymbolAddress((void**)&hl,   g_hl);

    const int M = NN, E = EE;
    const int TPB = 256;
    const int NBLK = (NB + 1023) / 1024;
    dim3 gemm_grid((M + 127) / 128, DH / 128);
    int agg_grid = (NB * 32 + TPB - 1) / TPB;
    int hw_grid = (M * (DH / 2) + TPB - 1) / TPB;

    // ---- CSR build ----
    zero_i<<<(NB + TPB - 1) / TPB, TPB>>>(deg, NB);
    zero_i<<<(NB + TPB - 1) / TPB, TPB>>>(pos, NB);
    count_kernel<<<(E + TPB - 1) / TPB, TPB>>>(dst, rel, E);
    scan_block<<<NBLK, 256>>>(deg, off, bsum, NB);
    scan_block<<<1, 256>>>(bsum, bsum, nullptr, NBLK);
    scan_add<<<NBLK, 256>>>(off, bsum, NB);
    place_kernel<<<(E + TPB - 1) / TPB, TPB>>>(src, dst, rel, E);

    // ---- pre-split weights and x ----
    split_w<<<(131072 + 255) / 256, 256>>>(rel_w1,  whi + OW_REL1,  wlo + OW_REL1,  131072);
    split_w<<<(32768  + 255) / 256, 256>>>(loop_w1, whi + OW_LOOP1, wlo + OW_LOOP1, 32768);
    split_w<<<(65536  + 255) / 256, 256>>>(hp_w1,   whi + OW_HP1,   wlo + OW_HP1,   65536);
    split_w<<<(65536  + 255) / 256, 256>>>(ht_w1,   whi + OW_HT1,   wlo + OW_HT1,   65536);
    split_w<<<(262144 + 255) / 256, 256>>>(rel_w2,  whi + OW_REL2,  wlo + OW_REL2,  262144);
    split_w<<<(65536  + 255) / 256, 256>>>(loop_w2, whi + OW_LOOP2, wlo + OW_LOOP2, 65536);
    split_w<<<(65536  + 255) / 256, 256>>>(hp_w2,   whi + OW_HP2,   wlo + OW_HP2,   65536);
    split_w<<<(65536  + 255) / 256, 256>>>(ht_w2,   whi + OW_HT2,   wlo + OW_HT2,   65536);
    split_w<<<(NN * DIN + 255) / 256, 256>>>(x, xh, xl, NN * DIN);

    // ---- layer 1 ----
    agg_gather<DIN><<<agg_grid, TPB>>>(x);
    gemm_mma<<<gemm_grid, TPB>>>(aggh, aggl, RR * DIN, whi + OW_REL1, wlo + OW_REL1,
                                 xh, xl, DIN, whi + OW_LOOP1, wlo + OW_LOOP1,
                                 rel_b1, loop_b1, nullptr, th, tl, M, DH, 1);
    gemm_mma<<<gemm_grid, TPB>>>(th, tl, DH, whi + OW_HP1, wlo + OW_HP1,
                                 nullptr, nullptr, 0, nullptr, nullptr,
                                 hp_b1, nullptr, pg, nullptr, nullptr, M, 2 * DH, 0);
    gemm_mma<<<gemm_grid, TPB>>>(th, tl, DH, whi + OW_HT1, wlo + OW_HT1,
                                 nullptr, nullptr, 0, nullptr, nullptr,
                                 ht_b1, nullptr, pg + DH, nullptr, nullptr, M, 2 * DH, 0);
    highway_kernel<<<hw_grid, TPB>>>(th, tl, pg, hbuf, hh, hl, M);

    // ---- layer 2 ----
    agg_gather<DH><<<agg_grid, TPB>>>(hbuf);
    gemm_mma<<<gemm_grid, TPB>>>(aggh, aggl, RR * DH, whi + OW_REL2, wlo + OW_REL2,
                                 hh, hl, DH, whi + OW_LOOP2, wlo + OW_LOOP2,
                                 rel_b2, loop_b2, nullptr, th, tl, M, DH, 1);
    gemm_mma<<<gemm_grid, TPB>>>(th, tl, DH, whi + OW_HP2, wlo + OW_HP2,
                                 nullptr, nullptr, 0, nullptr, nullptr,
                                 hp_b2, nullptr, pg, nullptr, nullptr, M, 2 * DH, 0);
    gemm_mma<<<gemm_grid, TPB>>>(th, tl, DH, whi + OW_HT2, wlo + OW_HT2,
                                 nullptr, nullptr, 0, nullptr, nullptr,
                                 ht_b2, nullptr, pg + DH, nullptr, nullptr, M, 2 * DH, 0);
    highway_kernel<<<hw_grid, TPB>>>(th, tl, pg, out, nullptr, nullptr, M);
}

// round 6
// speedup vs baseline: 1.0362x; 1.0362x over previous
#include <cuda_runtime.h>
#include <cuda_bf16.h>
#include <cstdint>
#include <cstddef>

#define NN   50000
#define EE   800000
#define RR   4
#define NB   (NN * RR)
#define DIN  128
#define DH   256
#define EPSF 1e-10f

// ---------------- scratch (static device globals) ------------------------------
__device__ int   g_deg[NB];
__device__ int   g_off[NB];
__device__ int   g_pos[NB];
__device__ int   g_bsum[256];
__device__ int   g_eidx[EE];

// split bf16 hi/lo planes for all GEMM A operands
__device__ uint16_t g_xh[(size_t)NN * DIN],       g_xl[(size_t)NN * DIN];
__device__ uint16_t g_aggh[(size_t)NN * RR * DH], g_aggl[(size_t)NN * RR * DH];
__device__ uint16_t g_th[(size_t)NN * DH],        g_tl[(size_t)NN * DH];
__device__ uint16_t g_hh[(size_t)NN * DH],        g_hl[(size_t)NN * DH];
__device__ float    g_h[(size_t)NN * DH];
__device__ float    g_pg[(size_t)NN * 2 * DH];

// pre-split weights
#define OW_REL1  0
#define OW_LOOP1 131072
#define OW_HP1   163840
#define OW_HT1   229376
#define OW_REL2  294912
#define OW_LOOP2 557056
#define OW_HP2   622592
#define OW_HT2   688128
#define WTOT     753664
__device__ uint16_t g_whi[WTOT];
__device__ uint16_t g_wlo[WTOT];

// ---------------- CSR build ------------------------------------------------------
__global__ void zero_i(int* __restrict__ p, int n) {
    int i = blockIdx.x * blockDim.x + threadIdx.x;
    if (i < n) p[i] = 0;
}

__global__ void count_kernel(const int* __restrict__ dst, const int* __restrict__ rel, int E) {
    int e = blockIdx.x * blockDim.x + threadIdx.x;
    if (e < E) atomicAdd(&g_deg[dst[e] * RR + rel[e]], 1);
}

__global__ void scan_block(const int* __restrict__ in, int* __restrict__ out,
                           int* __restrict__ bsum, int n) {
    __shared__ int wsum[8];
    int base = blockIdx.x * 1024;
    int t = threadIdx.x;
    int lane = t & 31, w = t >> 5;
    int v[4], s = 0;
#pragma unroll
    for (int j = 0; j < 4; j++) {
        int i = base + t * 4 + j;
        v[j] = (i < n) ? in[i] : 0;
        s += v[j];
    }
    int ps = s;
#pragma unroll
    for (int d = 1; d < 32; d <<= 1) {
        int y = __shfl_up_sync(~0u, ps, d);
        if (lane >= d) ps += y;
    }
    if (lane == 31) wsum[w] = ps;
    __syncthreads();
    if (w == 0) {
        int x = (lane < 8) ? wsum[lane] : 0;
#pragma unroll
        for (int d = 1; d < 8; d <<= 1) {
            int y = __shfl_up_sync(~0u, x, d);
            if (lane >= d) x += y;
        }
        if (lane < 8) wsum[lane] = x;
    }
    __syncthreads();
    int excl = ps - s + (w > 0 ? wsum[w - 1] : 0);
#pragma unroll
    for (int j = 0; j < 4; j++) {
        int i = base + t * 4 + j;
        if (i < n) out[i] = excl;
        excl += v[j];
    }
    if (t == 255 && bsum) bsum[blockIdx.x] = (w > 0 ? wsum[w - 1] : 0) + ps;
}

__global__ void scan_add(int* __restrict__ off, const int* __restrict__ bsum, int n) {
    int i = blockIdx.x * 1024 + threadIdx.x * 4;
    int a = bsum[blockIdx.x];
#pragma unroll
    for (int j = 0; j < 4; j++)
        if (i + j < n) off[i + j] += a;
}

__global__ void place_kernel(const int* __restrict__ src, const int* __restrict__ dst,
                             const int* __restrict__ rel, int E) {
    int e = blockIdx.x * blockDim.x + threadIdx.x;
    if (e >= E) return;
    int b = dst[e] * RR + rel[e];
    int slot = g_off[b] + atomicAdd(&g_pos[b], 1);
    g_eidx[slot] = src[e];
}

// ---------------- split helpers ---------------------------------------------------
__device__ __forceinline__ void split_bf(float v, uint16_t& h, uint16_t& l) {
    __nv_bfloat16 hb = __float2bfloat16_rn(v);
    float res = v - __bfloat162float(hb);
    h = __bfloat16_as_ushort(hb);
    l = __bfloat16_as_ushort(__float2bfloat16_rn(res));
}

__global__ void split_w(const float* __restrict__ w, uint16_t* __restrict__ hi,
                        uint16_t* __restrict__ lo, int n) {
    int i = blockIdx.x * blockDim.x + threadIdx.x;
    if (i >= n) return;
    uint16_t h, l;
    split_bf(w[i], h, l);
    hi[i] = h;
    lo[i] = l;
}

// ---------------- gather aggregation (writes split planes) ------------------------
template <int D>
__global__ void agg_gather(const float* __restrict__ x) {
    int gw = (blockIdx.x * blockDim.x + threadIdx.x) >> 5;
    int lane = threadIdx.x & 31;
    if (gw >= NB) return;
    int start = g_off[gw];
    int n = g_deg[gw];
    const float4* X = (const float4*)x;
    float4 a0 = make_float4(0.f, 0.f, 0.f, 0.f);
    float4 a1 = make_float4(0.f, 0.f, 0.f, 0.f);
    int k = 0;
    for (; k + 2 <= n; k += 2) {
        int s0 = g_eidx[start + k];
        int s1 = g_eidx[start + k + 1];
        const float4* r0 = X + (size_t)s0 * (D / 4);
        const float4* r1 = X + (size_t)s1 * (D / 4);
        float4 v0 = r0[lane], w0 = r1[lane];
        a0.x += v0.x + w0.x; a0.y += v0.y + w0.y;
        a0.z += v0.z + w0.z; a0.w += v0.w + w0.w;
        if (D == 256) {
            float4 v1 = r0[lane + 32], w1 = r1[lane + 32];
            a1.x += v1.x + w1.x; a1.y += v1.y + w1.y;
            a1.z += v1.z + w1.z; a1.w += v1.w + w1.w;
        }
    }
    if (k < n) {
        int s0 = g_eidx[start + k];
        const float4* r0 = X + (size_t)s0 * (D / 4);
        float4 v0 = r0[lane];
        a0.x += v0.x; a0.y += v0.y; a0.z += v0.z; a0.w += v0.w;
        if (D == 256) {
            float4 v1 = r0[lane + 32];
            a1.x += v1.x; a1.y += v1.y; a1.z += v1.z; a1.w += v1.w;
        }
    }
    float inv = 1.0f / ((float)n + EPSF);
    a0.x *= inv; a0.y *= inv; a0.z *= inv; a0.w *= inv;
    uint16_t h0, h1, h2, h3, l0, l1, l2, l3;
    split_bf(a0.x, h0, l0); split_bf(a0.y, h1, l1);
    split_bf(a0.z, h2, l2); split_bf(a0.w, h3, l3);
    uint2 hw = make_uint2((uint32_t)h0 | ((uint32_t)h1 << 16),
                          (uint32_t)h2 | ((uint32_t)h3 << 16));
    uint2 lw = make_uint2((uint32_t)l0 | ((uint32_t)l1 << 16),
                          (uint32_t)l2 | ((uint32_t)l3 << 16));
    ((uint2*)(g_aggh + (size_t)gw * D))[lane] = hw;
    ((uint2*)(g_aggl + (size_t)gw * D))[lane] = lw;
    if (D == 256) {
        a1.x *= inv; a1.y *= inv; a1.z *= inv; a1.w *= inv;
        split_bf(a1.x, h0, l0); split_bf(a1.y, h1, l1);
        split_bf(a1.z, h2, l2); split_bf(a1.w, h3, l3);
        hw = make_uint2((uint32_t)h0 | ((uint32_t)h1 << 16),
                        (uint32_t)h2 | ((uint32_t)h3 << 16));
        lw = make_uint2((uint32_t)l0 | ((uint32_t)l1 << 16),
                        (uint32_t)l2 | ((uint32_t)l3 << 16));
        ((uint2*)(g_aggh + (size_t)gw * D))[lane + 32] = hw;
        ((uint2*)(g_aggl + (size_t)gw * D))[lane + 32] = lw;
    }
}

// ---------------- highway elementwise ----------------------------------------------
__global__ void highway_kernel(const uint16_t* __restrict__ th, const uint16_t* __restrict__ tl,
                               const float* __restrict__ pg,
                               float* __restrict__ hf,
                               uint16_t* __restrict__ hh, uint16_t* __restrict__ hl,
                               int M) {
    int i = blockIdx.x * blockDim.x + threadIdx.x;
    if (i >= M * (DH / 2)) return;
    int e0 = i * 2;
    int n = e0 >> 8;
    int c = e0 & 255;
    const float* row = pg + (size_t)n * (2 * DH);
    float p0 = fmaxf(row[c], 0.f), p1 = fmaxf(row[c + 1], 0.f);
    float q0 = row[DH + c], q1 = row[DH + c + 1];
    float s0 = 1.0f / (1.0f + expf(-q0));
    float s1 = 1.0f / (1.0f + expf(-q1));
    float t0 = __bfloat162float(__ushort_as_bfloat16(th[e0])) +
               __bfloat162float(__ushort_as_bfloat16(tl[e0]));
    float t1 = __bfloat162float(__ushort_as_bfloat16(th[e0 + 1])) +
               __bfloat162float(__ushort_as_bfloat16(tl[e0 + 1]));
    float v0 = s0 * p0 + (1.0f - s0) * t0;
    float v1 = s1 * p1 + (1.0f - s1) * t1;
    if (hf) *(float2*)(hf + e0) = make_float2(v0, v1);
    if (hh) {
        uint16_t h0, h1, l0, l1;
        split_bf(v0, h0, l0);
        split_bf(v1, h1, l1);
        *(uint32_t*)(hh + e0) = (uint32_t)h0 | ((uint32_t)h1 << 16);
        *(uint32_t*)(hl + e0) = (uint32_t)l0 | ((uint32_t)l1 << 16);
    }
}

// ---------------- mma.sync / cp.async helpers ----------------------------------------
__device__ __forceinline__ uint32_t smem_u32(const void* p) {
    uint32_t a;
    asm("{ .reg .u64 t; cvta.to.shared.u64 t, %1; cvt.u32.u64 %0, t; }" : "=r"(a) : "l"(p));
    return a;
}
__device__ __forceinline__ void ldsm_x4(uint32_t* r, uint32_t addr) {
    asm volatile("ldmatrix.sync.aligned.m8n8.x4.shared.b16 {%0,%1,%2,%3}, [%4];"
                 : "=r"(r[0]), "=r"(r[1]), "=r"(r[2]), "=r"(r[3]) : "r"(addr));
}
__device__ __forceinline__ void ldsm_x4_t(uint32_t* r, uint32_t addr) {
    asm volatile("ldmatrix.sync.aligned.m8n8.x4.trans.shared.b16 {%0,%1,%2,%3}, [%4];"
                 : "=r"(r[0]), "=r"(r[1]), "=r"(r[2]), "=r"(r[3]) : "r"(addr));
}
__device__ __forceinline__ void mma_bf16(float* d, const uint32_t* a, uint32_t b0, uint32_t b1) {
    asm volatile(
        "mma.sync.aligned.m16n8k16.row.col.f32.bf16.bf16.f32 "
        "{%0,%1,%2,%3}, {%4,%5,%6,%7}, {%8,%9}, {%0,%1,%2,%3};"
        : "+f"(d[0]), "+f"(d[1]), "+f"(d[2]), "+f"(d[3])
        : "r"(a[0]), "r"(a[1]), "r"(a[2]), "r"(a[3]), "r"(b0), "r"(b1));
}
__device__ __forceinline__ void cp16(uint32_t dst, const void* src, bool pred) {
    int sz = pred ? 16 : 0;
    asm volatile("cp.async.cg.shared.global [%0], [%1], 16, %2;"
                 :: "r"(dst), "l"(src), "r"(sz) : "memory");
}
#define CP_COMMIT() asm volatile("cp.async.commit_group;" ::: "memory")
#define CP_WAIT1()  asm volatile("cp.async.wait_group 1;" ::: "memory")

// ---------------- bf16 pre-split dual-A GEMM, cp.async 3-stage ------------------------
// normal mode:  C[:,0:256] = act(A1@W1 + A2@W2 + b1 + b2)
// gate mode:    C[:,0:256] = A1@W1 + b1 ; C[:,256:512] = A1@W2 + b2  (K2==0, grid.y=4)
#define NSTG 3
#define A_STRIDE 80
#define A_BYTES  (128 * A_STRIDE)         // 10240
#define B_BYTES  8192                     // 16 k-rows hi (4KB) + 16 lo (4KB)
#define STAGE_BYTES (A_BYTES + B_BYTES)   // 18432
#define GEMM_SMEM (NSTG * STAGE_BYTES)    // 55296

__global__ void __launch_bounds__(256, 2)
gemm_mma(const uint16_t* __restrict__ A1h, const uint16_t* __restrict__ A1l, int K1,
         const uint16_t* __restrict__ W1h, const uint16_t* __restrict__ W1l,
         const uint16_t* __restrict__ A2h, const uint16_t* __restrict__ A2l, int K2,
         const uint16_t* __restrict__ W2h, const uint16_t* __restrict__ W2l,
         const float* __restrict__ b1, const float* __restrict__ b2,
         float* __restrict__ Cf, uint16_t* __restrict__ Ch, uint16_t* __restrict__ Cl,
         int M, int ldc, int act, int gate_mode) {
    extern __shared__ char sm[];
    uint32_t smBase = smem_u32(sm);

    int tid  = threadIdx.x;
    int warp = tid >> 5;
    int lane = tid & 31;
    int warpM = warp >> 1;
    int warpN = warp & 1;
    int rowBase = blockIdx.x * 128;
    int colBase = blockIdx.y * 128;

    // weight/bias selection (gate mode: blocks with colBase>=256 use the 2nd set)
    const uint16_t *WhA = W1h, *WlA = W1l;
    const float* bsel = b1;
    int wcol = colBase;
    if (gate_mode && colBase >= DH) {
        WhA = W2h; WlA = W2l; bsel = b2; wcol = colBase - DH;
    }

    float acc[2][8][4];
#pragma unroll
    for (int i = 0; i < 2; i++)
#pragma unroll
        for (int j = 0; j < 8; j++)
#pragma unroll
            for (int q = 0; q < 4; q++) acc[i][j][q] = 0.f;

    int nt1 = K1 >> 4, nt2 = K2 >> 4;
    int nt = nt1 + nt2;

    // per-thread load coordinates
    int aRow  = tid >> 2;          // A: 512 chunks of 16B -> 2/thread
    int aPart = tid & 3;           // 0,1: hi halves; 2,3: lo halves
    int bR    = (tid >> 4) & 15;   // B: 16 k-rows x 16 col-chunks x 2 planes
    int bC16  = tid & 15;

    // ---- stage loader ----
    auto issue_stage = [&](int t) {
        uint32_t stg = smBase + (uint32_t)(t % NSTG) * STAGE_BYTES;
        const uint16_t *Ah, *Al, *Wh, *Wl;
        int K, k0;
        if (t < nt1) { Ah = A1h; Al = A1l; Wh = WhA; Wl = WlA; K = K1; k0 = t * 16; }
        else { Ah = A2h; Al = A2l; Wh = W2h; Wl = W2l; K = K2; k0 = (t - nt1) * 16; }
#pragma unroll
        for (int i = 0; i < 2; ++i) {
            int row = aRow + i * 64;
            int gr = rowBase + row;
            bool ok = gr < M;
            int grc = ok ? gr : (M - 1);
            const uint16_t* base = (aPart < 2) ? Ah : Al;
            cp16(stg + row * A_STRIDE + aPart * 16,
                 base + (size_t)grc * K + k0 + (aPart & 1) * 8, ok);
        }
#pragma unroll
        for (int i = 0; i < 2; ++i) {
            const uint16_t* base = i ? Wl : Wh;
            uint32_t dst = stg + A_BYTES + i * 4096 + bR * 256
                         + ((uint32_t)(bC16 * 16) ^ ((bR & 7) << 4));
            cp16(dst, base + (size_t)(k0 + bR) * DH + wcol + bC16 * 8, true);
        }
    };

    // ---- prologue: stages 0, 1 ----
    issue_stage(0); CP_COMMIT();
    if (nt > 1) issue_stage(1);
    CP_COMMIT();

    for (int t = 0; t < nt; ++t) {
        CP_WAIT1();
        __syncthreads();

        // issue t+2 (overlaps mma below); always commit to keep group count uniform
        if (t + 2 < nt) issue_stage(t + 2);
        CP_COMMIT();

        uint32_t stg = smBase + (uint32_t)(t % NSTG) * STAGE_BYTES;
        uint32_t aBase = stg;
        uint32_t bBase = stg + A_BYTES;

        uint32_t ahi[2][4], alo[2][4], bhi[4][4], blo[4][4];
#pragma unroll
        for (int mt = 0; mt < 2; ++mt) {
            int row = warpM * 32 + mt * 16 + (lane & 15);
            uint32_t ad = aBase + row * A_STRIDE + ((lane >> 4) * 8) * 2;
            ldsm_x4(ahi[mt], ad);
            ldsm_x4(alo[mt], ad + 32);
        }
#pragma unroll
        for (int bt = 0; bt < 4; ++bt) {
            int k = lane & 15;
            uint32_t cb = (uint32_t)(warpN * 128 + bt * 32 + (lane >> 4) * 16);
            uint32_t bd = bBase + k * 256 + (cb ^ ((k & 7) << 4));
            ldsm_x4_t(bhi[bt], bd);
            ldsm_x4_t(blo[bt], bd + 4096);
        }

#pragma unroll
        for (int mt = 0; mt < 2; ++mt) {
#pragma unroll
            for (int bt = 0; bt < 4; ++bt) {
                mma_bf16(acc[mt][bt * 2 + 0], ahi[mt], bhi[bt][0], bhi[bt][1]);
                mma_bf16(acc[mt][bt * 2 + 1], ahi[mt], bhi[bt][2], bhi[bt][3]);
                mma_bf16(acc[mt][bt * 2 + 0], ahi[mt], blo[bt][0], blo[bt][1]);
                mma_bf16(acc[mt][bt * 2 + 1], ahi[mt], blo[bt][2], blo[bt][3]);
                mma_bf16(acc[mt][bt * 2 + 0], alo[mt], bhi[bt][0], bhi[bt][1]);
                mma_bf16(acc[mt][bt * 2 + 1], alo[mt], bhi[bt][2], bhi[bt][3]);
            }
        }
        __syncthreads();
    }

    // ---- epilogue ----
#pragma unroll
    for (int mt = 0; mt < 2; ++mt) {
        int r0 = rowBase + warpM * 32 + mt * 16 + (lane >> 2);
#pragma unroll
        for (int j = 0; j < 8; ++j) {
            int col = colBase + warpN * 64 + j * 8 + (lane & 3) * 2;
            float bias0, bias1;
            if (gate_mode) {
                bias0 = bsel[col & 255];
                bias1 = bsel[(col + 1) & 255];
            } else {
                bias0 = b1[col]; bias1 = b1[col + 1];
                if (b2) { bias0 += b2[col]; bias1 += b2[col + 1]; }
            }
            float v0 = acc[mt][j][0] + bias0;
            float v1 = acc[mt][j][1] + bias1;
            float v2 = acc[mt][j][2] + bias0;
            float v3 = acc[mt][j][3] + bias1;
            if (act) {
                v0 = fmaxf(v0, 0.f); v1 = fmaxf(v1, 0.f);
                v2 = fmaxf(v2, 0.f); v3 = fmaxf(v3, 0.f);
            }
            if (Ch) {
                uint16_t h0, h1, l0, l1;
                if (r0 < M) {
                    split_bf(v0, h0, l0); split_bf(v1, h1, l1);
                    *(uint32_t*)(Ch + (size_t)r0 * ldc + col) = (uint32_t)h0 | ((uint32_t)h1 << 16);
                    *(uint32_t*)(Cl + (size_t)r0 * ldc + col) = (uint32_t)l0 | ((uint32_t)l1 << 16);
                }
                if (r0 + 8 < M) {
                    split_bf(v2, h0, l0); split_bf(v3, h1, l1);
                    *(uint32_t*)(Ch + (size_t)(r0 + 8) * ldc + col) = (uint32_t)h0 | ((uint32_t)h1 << 16);
                    *(uint32_t*)(Cl + (size_t)(r0 + 8) * ldc + col) = (uint32_t)l0 | ((uint32_t)l1 << 16);
                }
            } else {
                if (r0 < M)     *(float2*)(Cf + (size_t)r0 * ldc + col)       = make_float2(v0, v1);
                if (r0 + 8 < M) *(float2*)(Cf + (size_t)(r0 + 8) * ldc + col) = make_float2(v2, v3);
            }
        }
    }
}

// ---------------- launcher ------------------------------------------------------------
extern "C" void kernel_launch(void* const* d_in, const int* in_sizes, int n_in,
                              void* d_out, int out_size) {
    const float* x       = (const float*)d_in[0];
    const int*   src     = (const int*)d_in[1];
    const int*   dst     = (const int*)d_in[2];
    const int*   rel     = (const int*)d_in[3];
    const float* rel_w1  = (const float*)d_in[4];
    const float* rel_b1  = (const float*)d_in[5];
    const float* loop_w1 = (const float*)d_in[6];
    const float* loop_b1 = (const float*)d_in[7];
    const float* hp_w1   = (const float*)d_in[8];
    const float* hp_b1   = (const float*)d_in[9];
    const float* ht_w1   = (const float*)d_in[10];
    const float* ht_b1   = (const float*)d_in[11];
    const float* rel_w2  = (const float*)d_in[12];
    const float* rel_b2  = (const float*)d_in[13];
    const float* loop_w2 = (const float*)d_in[14];
    const float* loop_b2 = (const float*)d_in[15];
    const float* hp_w2   = (const float*)d_in[16];
    const float* hp_b2   = (const float*)d_in[17];
    const float* ht_w2   = (const float*)d_in[18];
    const float* ht_b2   = (const float*)d_in[19];
    float* out = (float*)d_out;

    float *hbuf, *pg;
    int *deg, *off, *pos, *bsum;
    uint16_t *whi, *wlo, *xh, *xl, *aggh, *aggl, *th, *tl, *hh, *hl;
    cudaGetSymbolAddress((void**)&hbuf, g_h);
    cudaGetSymbolAddress((void**)&pg,   g_pg);
    cudaGetSymbolAddress((void**)&deg,  g_deg);
    cudaGetSymbolAddress((void**)&off,  g_off);
    cudaGetSymbolAddress((void**)&pos,  g_pos);
    cudaGetSymbolAddress((void**)&bsum, g_bsum);
    cudaGetSymbolAddress((void**)&whi,  g_whi);
    cudaGetSymbolAddress((void**)&wlo,  g_wlo);
    cudaGetSymbolAddress((void**)&xh,   g_xh);
    cudaGetSymbolAddress((void**)&xl,   g_xl);
    cudaGetSymbolAddress((void**)&aggh, g_aggh);
    cudaGetSymbolAddress((void**)&aggl, g_aggl);
    cudaGetSymbolAddress((void**)&th,   g_th);
    cudaGetSymbolAddress((void**)&tl,   g_tl);
    cudaGetSymbolAddress((void**)&hh,   g_hh);
    cudaGetSymbolAddress((void**)&hl,   g_hl);

    cudaFuncSetAttribute(gemm_mma, cudaFuncAttributeMaxDynamicSharedMemorySize, GEMM_SMEM);

    const int M = NN, E = EE;
    const int TPB = 256;
    const int NBLK = (NB + 1023) / 1024;
    dim3 rgc_grid((M + 127) / 128, 2);
    dim3 hw_gemm_grid((M + 127) / 128, 4);
    int agg_grid = (NB * 32 + TPB - 1) / TPB;
    int hw_grid = (M * (DH / 2) + TPB - 1) / TPB;

    // ---- CSR build ----
    zero_i<<<(NB + TPB - 1) / TPB, TPB>>>(deg, NB);
    zero_i<<<(NB + TPB - 1) / TPB, TPB>>>(pos, NB);
    count_kernel<<<(E + TPB - 1) / TPB, TPB>>>(dst, rel, E);
    scan_block<<<NBLK, 256>>>(deg, off, bsum, NB);
    scan_block<<<1, 256>>>(bsum, bsum, nullptr, NBLK);
    scan_add<<<NBLK, 256>>>(off, bsum, NB);
    place_kernel<<<(E + TPB - 1) / TPB, TPB>>>(src, dst, rel, E);

    // ---- pre-split weights and x ----
    split_w<<<(131072 + 255) / 256, 256>>>(rel_w1,  whi + OW_REL1,  wlo + OW_REL1,  131072);
    split_w<<<(32768  + 255) / 256, 256>>>(loop_w1, whi + OW_LOOP1, wlo + OW_LOOP1, 32768);
    split_w<<<(65536  + 255) / 256, 256>>>(hp_w1,   whi + OW_HP1,   wlo + OW_HP1,   65536);
    split_w<<<(65536  + 255) / 256, 256>>>(ht_w1,   whi + OW_HT1,   wlo + OW_HT1,   65536);
    split_w<<<(262144 + 255) / 256, 256>>>(rel_w2,  whi + OW_REL2,  wlo + OW_REL2,  262144);
    split_w<<<(65536  + 255) / 256, 256>>>(loop_w2, whi + OW_LOOP2, wlo + OW_LOOP2, 65536);
    split_w<<<(65536  + 255) / 256, 256>>>(hp_w2,   whi + OW_HP2,   wlo + OW_HP2,   65536);
    split_w<<<(65536  + 255) / 256, 256>>>(ht_w2,   whi + OW_HT2,   wlo + OW_HT2,   65536);
    split_w<<<(NN * DIN + 255) / 256, 256>>>(x, xh, xl, NN * DIN);

    // ---- layer 1 ----
    agg_gather<DIN><<<agg_grid, TPB>>>(x);
    gemm_mma<<<rgc_grid, TPB, GEMM_SMEM>>>(
        aggh, aggl, RR * DIN, whi + OW_REL1, wlo + OW_REL1,
        xh, xl, DIN, whi + OW_LOOP1, wlo + OW_LOOP1,
        rel_b1, loop_b1, nullptr, th, tl, M, DH, 1, 0);
    gemm_mma<<<hw_gemm_grid, TPB, GEMM_SMEM>>>(
        th, tl, DH, whi + OW_HP1, wlo + OW_HP1,
        nullptr, nullptr, 0, whi + OW_HT1, wlo + OW_HT1,
        hp_b1, ht_b1, pg, nullptr, nullptr, M, 2 * DH, 0, 1);
    highway_kernel<<<hw_grid, TPB>>>(th, tl, pg, hbuf, hh, hl, M);

    // ---- layer 2 ----
    agg_gather<DH><<<agg_grid, TPB>>>(hbuf);
    gemm_mma<<<rgc_grid, TPB, GEMM_SMEM>>>(
        aggh, aggl, RR * DH, whi + OW_REL2, wlo + OW_REL2,
        hh, hl, DH, whi + OW_LOOP2, wlo + OW_LOOP2,
        rel_b2, loop_b2, nullptr, th, tl, M, DH, 1, 0);
    gemm_mma<<<hw_gemm_grid, TPB, GEMM_SMEM>>>(
        th, tl, DH, whi + OW_HP2, wlo + OW_HP2,
        nullptr, nullptr, 0, whi + OW_HT2, wlo + OW_HT2,
        hp_b2, ht_b2, pg, nullptr, nullptr, M, 2 * DH, 0, 1);
    highway_kernel<<<hw_grid, TPB>>>(th, tl, pg, out, nullptr, nullptr, M);
}